// round 11
// baseline (speedup 1.0000x reference)
#include <cuda_runtime.h>

// Problem constants
#define NB 1024
#define TPTS 512
#define CTXN 23
#define D 320
#define NL 5
#define NH 8
#define DHD 40
#define FFD 1280
#define NCOEF 49
#define S 24
#define NT 640          // threads per CTA (20 warps)
#define NWARP 20
#define NCOL 320        // column-threads per GEMM; 2 row-groups of 12 rows
#define QVS 965         // padded row stride for qkv smem
#define HS 24           // transposed-activation row stride (exact; rg offsets 0/48B -> 16B aligned)
#define GS 28           // ffn intermediate row stride (112B; k*112 and rg*48 both 16B aligned)

typedef unsigned long long ull;

// Shared-memory layout (in floats) — identical to R10
#define XS_OFF 0                         // x residual   [24][320]      7680
#define HST_OFF 7680                     // LN out (T)   [320][24]      7680
#define QV_OFF 15360                     // qkv [24][965] = 23160 ; aliased: gstc [640][28]=17920 / head u
#define SC_OFF 38520                     // scores       [8][24][25]    4800
#define HH_OFF 43320                     // head LN vec  [320]
#define CC_OFF 43640                     // cheb coeffs  [64]
#define ST_OFF 43704                     // stats        [8]
#define SMEM_FLOATS 43712
#define SMEM_BYTES (SMEM_FLOATS * 4)

// Repacked weights (prep kernel fills these once per launch).
__device__ float g_Wqkvp[NL * 320 * 960];   // [l][k][ f2: 320*2 | f1: 320 ]  (o = 3*ct + j)
__device__ float g_Woutp[NL * 320 * 320];   // [l][k][o]   plain transpose (o = ct)
__device__ float g_W1p[NL * 320 * 1280];    // [l][c][k][q]  plain, o = c*640 + q, q = 2*ct + j
__device__ float g_W2p[NL * 1280 * 320];    // [l][c][kl][o] plain, o = ct
__device__ float g_Wh1t[320 * 320];

__global__ void prep_kernel(const float* __restrict__ Win, const float* __restrict__ Wout,
                            const float* __restrict__ W1, const float* __restrict__ W2,
                            const float* __restrict__ Wh1) {
    long start = (long)blockIdx.x * blockDim.x + threadIdx.x;
    long stride = (long)gridDim.x * blockDim.x;
    // QKV: split f2/f1 thread-major pack: o = 3*ct + j
    for (long i = start; i < (long)NL * 320 * 960; i += stride) {
        long l = i / 307200, r = i % 307200;
        long k = r / 960, q = r % 960;
        long o;
        if (q < 640) { long ct = q >> 1, e = q & 1; o = 3 * ct + e; }
        else         { long ct = q - 640; o = 3 * ct + 2; }
        g_Wqkvp[i] = Win[l * 307200 + o * 320 + k];
    }
    for (long i = start; i < (long)NL * 320 * 320; i += stride) {
        long l = i / 102400, r = i % 102400;
        long k = r / 320, o = r % 320;
        g_Woutp[i] = Wout[l * 102400 + o * 320 + k];
    }
    for (long i = start; i < (long)NL * 2 * 320 * 640; i += stride) {
        long lc = i / 204800, r = i % 204800;
        long k = r / 640, q = r % 640;
        long l = lc / 2, c = lc % 2;
        g_W1p[i] = W1[l * 409600 + (c * 640 + q) * 320 + k];
    }
    for (long i = start; i < (long)NL * 2 * 640 * 320; i += stride) {
        long lc = i / 204800, r = i % 204800;
        long kl = r / 320, o = r % 320;
        long l = lc / 2, c = lc % 2;
        g_W2p[i] = W2[l * 409600 + o * 1280 + (c * 640 + kl)];
    }
    for (long i = start; i < (long)320 * 320; i += stride) {
        long k = i / 320, o = i % 320;
        g_Wh1t[i] = Wh1[o * 320 + k];
    }
}

__device__ __forceinline__ ull ffma2(ull a, ull b, ull c) {
    ull d;
    asm("fma.rn.f32x2 %0, %1, %2, %3;" : "=l"(d) : "l"(a), "l"(b), "l"(c));
    return d;
}
__device__ __forceinline__ ull bcast2(float x) {
    ull d;
    asm("mov.b64 %0, {%1, %1};" : "=l"(d) : "f"(x));
    return d;
}
__device__ __forceinline__ float2 unpack2(ull a) {
    float2 v;
    asm("mov.b64 {%0, %1}, %2;" : "=f"(v.x), "=f"(v.y) : "l"(a));
    return v;
}
__device__ __forceinline__ float gelu_exact(float x) {
    return 0.5f * x * (1.0f + erff(x * 0.70710678118654752f));
}
__device__ __forceinline__ float warp_sum(float v) {
#pragma unroll
    for (int o = 16; o; o >>= 1) v += __shfl_xor_sync(0xffffffffu, v, o);
    return v;
}

// Load this row-group's 6 activation row-pairs (12 rows), 16B-aligned broadcast.
__device__ __forceinline__ void lda6(ull* __restrict__ a, const ull* __restrict__ hp) {
    ulonglong2 q0 = *(const ulonglong2*)(hp);
    ulonglong2 q1 = *(const ulonglong2*)(hp + 2);
    ulonglong2 q2 = *(const ulonglong2*)(hp + 4);
    a[0] = q0.x; a[1] = q0.y; a[2] = q1.x; a[3] = q1.y; a[4] = q2.x; a[5] = q2.y;
}

// One k-step of FMAs on preloaded activations: O weight-broadcast x 6 row-pairs.
template <int O>
__device__ __forceinline__ void fmaacc(const float* __restrict__ w, const ull* __restrict__ a,
                                       ull* __restrict__ acc) {
#pragma unroll
    for (int j = 0; j < O; j++) {
        ull wb = bcast2(w[j]);
#pragma unroll
        for (int p = 0; p < 6; p++) acc[j * 6 + p] = ffma2(wb, a[p], acc[j * 6 + p]);
    }
}

template <int O, int OFF3>
__device__ __forceinline__ void ldw(float* __restrict__ w, const float* __restrict__ wk, int ct) {
    if (O == 1) w[0] = __ldg(wk + ct);
    if (O == 2) {
        float2 v = __ldg((const float2*)(wk + ct * 2));
        w[0] = v.x; w[1] = v.y;
    }
    if (O == 3) {
        float2 v = __ldg((const float2*)(wk + ct * 2));
        w[0] = v.x; w[1] = v.y;
        w[2] = __ldg(wk + OFF3 + ct);
    }
}

// Register-blocked GEMM: 4-deep weight prefetch + double-buffered activations.
// Thread = (ct, rg): O output columns x 12 rows (6 f32x2 pairs).
template <int O, int WS, int HSU, int K, int OFF3>
__device__ __forceinline__ void gemmT(const float* __restrict__ Wp, int ct,
                                      const ull* __restrict__ hin, ull* __restrict__ acc) {
#pragma unroll
    for (int i = 0; i < O * 6; i++) acc[i] = 0ull;
    float w[4][O];
    ull a[2][6];
#pragma unroll
    for (int d = 0; d < 4; d++) ldw<O, OFF3>(w[d], Wp + d * WS, ct);
    lda6(a[0], hin);
#pragma unroll 4
    for (int k = 0; k < K - 4; k++) {
        lda6(a[(k + 1) & 1], hin + (k + 1) * HSU);
        fmaacc<O>(w[k & 3], a[k & 1], acc);
        ldw<O, OFF3>(w[k & 3], Wp + (k + 4) * WS, ct);
    }
#pragma unroll
    for (int k = K - 4; k < K - 1; k++) {
        lda6(a[(k + 1) & 1], hin + (k + 1) * HSU);
        fmaacc<O>(w[k & 3], a[k & 1], acc);
    }
    fmaacc<O>(w[3], a[1], acc);  // k = K-1: (K-1)&3 == 3, (K-1)&1 == 1 for K % 4 == 0
}

// LayerNorm of xs[24][320] -> transposed hst[k][HS]+r, one warp per row.
__device__ __forceinline__ void layernorm24(const float* __restrict__ xs, float* __restrict__ hst,
                                            const float* __restrict__ w, const float* __restrict__ b,
                                            int warp, int lane) {
    for (int r = warp; r < S; r += NWARP) {
        const float* row = xs + r * D;
        float s = 0.f;
        for (int k = lane; k < D; k += 32) s += row[k];
        s = warp_sum(s);
        float mean = s * (1.f / D);
        float s2 = 0.f;
        for (int k = lane; k < D; k += 32) {
            float v = row[k] - mean;
            s2 += v * v;
        }
        s2 = warp_sum(s2);
        float rstd = rsqrtf(s2 * (1.f / D) + 1e-5f);
        for (int k = lane; k < D; k += 32)
            hst[k * HS + r] = (row[k] - mean) * rstd * w[k] + b[k];
    }
}

__global__ __launch_bounds__(NT, 1) void fused_kernel(
    const float* __restrict__ k_norm, const float* __restrict__ ctx,
    const float* __restrict__ W_e, const float* __restrict__ b_e,
    const float* __restrict__ cls,
    const float* __restrict__ ln1_w, const float* __restrict__ ln1_b,
    const float* __restrict__ b_in, const float* __restrict__ b_out,
    const float* __restrict__ ln2_w, const float* __restrict__ ln2_b,
    const float* __restrict__ b1, const float* __restrict__ b2,
    const float* __restrict__ hln_w, const float* __restrict__ hln_b,
    const float* __restrict__ bh1, const float* __restrict__ Wh2,
    const float* __restrict__ bh2, float* __restrict__ out) {
    extern __shared__ float sm[];
    float* xs = sm + XS_OFF;
    float* hst = sm + HST_OFF;
    float* qv = sm + QV_OFF;
    float* gstc = sm + QV_OFF;   // ffn intermediate aliases qv: [640][28]
    float* sc = sm + SC_OFF;

    const int b = blockIdx.x;
    const int tid = threadIdx.x;
    const int warp = tid >> 5;
    const int lane = tid & 31;
    const int ct = tid % NCOL;       // warp-uniform row group (warps 0-9 -> rg 0, 10-19 -> rg 1)
    const int rg = tid / NCOL;       // 0..1
    const int rb = rg * 12;
    const ull* hstu = (const ull*)(hst) + rg * 6;
    const ull* gstu = (const ull*)(gstc) + rg * 6;

    // ---- build x: row 0 = cls, rows 1..23 = ctx*W_e + b_e ----
    for (int i = tid; i < S * D; i += NT) {
        int r = i / D, d = i % D;
        xs[i] = (r == 0) ? cls[d] : ctx[(long)b * CTXN + (r - 1)] * W_e[d] + b_e[d];
    }
    __syncthreads();

    for (int l = 0; l < NL; l++) {
        // ---- LN1 ----
        layernorm24(xs, hst, ln1_w + l * D, ln1_b + l * D, warp, lane);
        __syncthreads();

        // ---- QKV GEMM: 3 outputs x 12 rows per thread ----
        {
            ull acc[18];
            gemmT<3, 960, 12, 320, 640>(g_Wqkvp + l * 307200, ct, hstu, acc);
            int ob = ct * 3;
#pragma unroll
            for (int j = 0; j < 3; j++) {
                int o = ob + j;
                float bias = b_in[l * 960 + o];
#pragma unroll
                for (int p = 0; p < 6; p++) {
                    float2 v = unpack2(acc[j * 6 + p]);
                    qv[(rb + 2 * p) * QVS + o] = v.x + bias;
                    qv[(rb + 2 * p + 1) * QVS + o] = v.y + bias;
                }
            }
        }
        __syncthreads();

        // ---- attention: one warp per head; output written transposed into hst ----
        if (warp < NH) {
            const int h = warp;
            const float scale = 0.15811388300841897f;  // 1/sqrt(40)
            for (int idx = lane; idx < S * S; idx += 32) {
                int qr = idx / S, kc = idx % S;
                const float* qp = qv + qr * QVS + h * DHD;
                const float* kp = qv + kc * QVS + D + h * DHD;
                float s = 0.f;
#pragma unroll
                for (int d = 0; d < DHD; d++) s += qp[d] * kp[d];
                sc[(h * S + qr) * 25 + kc] = s * scale;
            }
            __syncwarp();
            if (lane < S) {
                float* row = sc + (h * S + lane) * 25;
                float mx = -1e30f;
#pragma unroll
                for (int c = 0; c < S; c++) mx = fmaxf(mx, row[c]);
                float sum = 0.f;
#pragma unroll
                for (int c = 0; c < S; c++) {
                    float e = expf(row[c] - mx);
                    row[c] = e;
                    sum += e;
                }
                float inv = 1.f / sum;
#pragma unroll
                for (int c = 0; c < S; c++) row[c] *= inv;
            }
            __syncwarp();
            for (int idx = lane; idx < S * DHD; idx += 32) {
                int r = idx / DHD, d = idx % DHD;
                const float* ar = sc + (h * S + r) * 25;
                const float* vp = qv + 2 * D + h * DHD + d;
                float s = 0.f;
#pragma unroll
                for (int c = 0; c < S; c++) s += ar[c] * vp[c * QVS];
                hst[(h * DHD + d) * HS + r] = s;  // transposed attn output
            }
        }
        __syncthreads();

        // ---- output projection (residual add): 1 output x 12 rows ----
        {
            ull acc[6];
            gemmT<1, 320, 12, 320, 0>(g_Woutp + l * 102400, ct, hstu, acc);
            int o = ct;
            float bias = b_out[l * D + o];
#pragma unroll
            for (int p = 0; p < 6; p++) {
                float2 v = unpack2(acc[p]);
                xs[(rb + 2 * p) * D + o] += v.x + bias;
                xs[(rb + 2 * p + 1) * D + o] += v.y + bias;
            }
        }
        __syncthreads();

        // ---- LN2 ----
        layernorm24(xs, hst, ln2_w + l * D, ln2_b + l * D, warp, lane);
        __syncthreads();

        // ---- FFN: 2 chunks of 640 ff units ----
        for (int c = 0; c < 2; c++) {
            {
                ull acc[12];
                gemmT<2, 640, 12, 320, 0>(g_W1p + (l * 2 + c) * 204800, ct, hstu, acc);
                int ob = ct * 2;
#pragma unroll
                for (int j = 0; j < 2; j++) {
                    int ol = ob + j;
                    float bias = b1[l * FFD + c * 640 + ol];
#pragma unroll
                    for (int p = 0; p < 6; p++) {
                        float2 v = unpack2(acc[j * 6 + p]);
                        float2 g;
                        g.x = gelu_exact(v.x + bias);
                        g.y = gelu_exact(v.y + bias);
                        *(float2*)(gstc + ol * GS + rb + 2 * p) = g;
                    }
                }
            }
            __syncthreads();
            {
                ull acc[6];
                gemmT<1, 320, 14, 640, 0>(g_W2p + (l * 2 + c) * 204800, ct, gstu, acc);
                int o = ct;
                float bias = (c == 0) ? b2[l * D + o] : 0.f;
#pragma unroll
                for (int p = 0; p < 6; p++) {
                    float2 v = unpack2(acc[p]);
                    xs[(rb + 2 * p) * D + o] += v.x + bias;
                    xs[(rb + 2 * p + 1) * D + o] += v.y + bias;
                }
            }
            __syncthreads();
        }
    }

    // ---- head: LN(x[0]) ----
    if (warp == 0) {
        float s = 0.f;
        for (int k = lane; k < D; k += 32) s += xs[k];
        s = warp_sum(s);
        float mean = s * (1.f / D);
        float s2 = 0.f;
        for (int k = lane; k < D; k += 32) {
            float v = xs[k] - mean;
            s2 += v * v;
        }
        s2 = warp_sum(s2);
        if (lane == 0) {
            sm[ST_OFF] = mean;
            sm[ST_OFF + 1] = rsqrtf(s2 * (1.f / D) + 1e-5f);
        }
    }
    __syncthreads();
    if (tid < D) {
        float mean = sm[ST_OFF], rstd = sm[ST_OFF + 1];
        int k = tid;
        sm[HH_OFF + k] = (xs[k] - mean) * rstd * hln_w[k] + hln_b[k];
    }
    __syncthreads();

    // ---- u = gelu(hh @ Wh1^T + bh1): one output per thread (u aliases qv) ----
    if (tid < D) {
        int o = tid;
        float acc = bh1[o];
        const float* wp = g_Wh1t + o;
        const float* hh = sm + HH_OFF;
#pragma unroll 4
        for (int k = 0; k < D; k++) {
            acc = fmaf(hh[k], *wp, acc);
            wp += D;
        }
        qv[o] = gelu_exact(acc);
    }
    __syncthreads();

    // ---- c[j] = u @ Wh2^T + bh2 ----
    for (int j = warp; j < NCOEF; j += NWARP) {
        float s = 0.f;
        for (int k = lane; k < D; k += 32) s += qv[k] * Wh2[j * D + k];
        s = warp_sum(s);
        if (lane == 0) sm[CC_OFF + j] = s + bh2[j];
    }
    __syncthreads();

    // ---- Chebyshev sum + sigmoid over T=512 points ----
    const float* cc = sm + CC_OFF;
    for (int t = tid; t < TPTS; t += NT) {
        float x = k_norm[(long)b * TPTS + t];
        float tp = 1.f, tc = x;
        float z = cc[0] + cc[1] * x;
#pragma unroll
        for (int n = 2; n < NCOEF; n++) {
            float tn = 2.f * x * tc - tp;
            z = fmaf(cc[n], tn, z);
            tp = tc;
            tc = tn;
        }
        out[(long)b * TPTS + t] = 1.f / (1.f + expf(-z));
    }
}

extern "C" void kernel_launch(void* const* d_in, const int* in_sizes, int n_in,
                              void* d_out, int out_size) {
    (void)in_sizes; (void)n_in; (void)out_size;
    const float* k_norm = (const float*)d_in[0];
    const float* ctx = (const float*)d_in[1];
    const float* W_e = (const float*)d_in[2];
    const float* b_e = (const float*)d_in[3];
    const float* cls = (const float*)d_in[4];
    const float* ln1_w = (const float*)d_in[5];
    const float* ln1_b = (const float*)d_in[6];
    const float* W_in = (const float*)d_in[7];
    const float* b_in = (const float*)d_in[8];
    const float* W_out = (const float*)d_in[9];
    const float* b_out = (const float*)d_in[10];
    const float* ln2_w = (const float*)d_in[11];
    const float* ln2_b = (const float*)d_in[12];
    const float* W1 = (const float*)d_in[13];
    const float* b1 = (const float*)d_in[14];
    const float* W2 = (const float*)d_in[15];
    const float* b2 = (const float*)d_in[16];
    const float* hln_w = (const float*)d_in[17];
    const float* hln_b = (const float*)d_in[18];
    const float* Wh1 = (const float*)d_in[19];
    const float* bh1 = (const float*)d_in[20];
    const float* Wh2 = (const float*)d_in[21];
    const float* bh2 = (const float*)d_in[22];
    float* out = (float*)d_out;

    cudaFuncSetAttribute(fused_kernel, cudaFuncAttributeMaxDynamicSharedMemorySize, SMEM_BYTES);

    prep_kernel<<<512, 256>>>(W_in, W_out, W1, W2, Wh1);
    fused_kernel<<<NB, NT, SMEM_BYTES>>>(k_norm, ctx, W_e, b_e, cls, ln1_w, ln1_b,
                                         b_in, b_out, ln2_w, ln2_b, b1, b2,
                                         hln_w, hln_b, bh1, Wh2, bh2, out);
}

// round 14
// speedup vs baseline: 1.1959x; 1.1959x over previous
#include <cuda_runtime.h>

// Problem constants
#define NB 1024
#define TPTS 512
#define CTXN 23
#define D 320
#define NL 5
#define NH 8
#define DHD 40
#define FFD 1280
#define NCOEF 49
#define S 24
#define NT 480          // threads per CTA (15 warps)
#define NWARP 15
#define NCOL 160        // column-threads per GEMM; 3 row-groups of 8 rows
#define QVS 965         // padded row stride for qkv smem
#define HS 24           // transposed-activation row stride (exact; rows 96B -> 16B aligned)
#define GS 28           // ffn intermediate row stride (112B -> 16B aligned)

typedef unsigned long long ull;

// Shared-memory layout (in floats)
#define XS_OFF 0                         // x residual   [24][320]      7680
#define HST_OFF 7680                     // LN out (T)   [320][24]      7680
#define QV_OFF 15360                     // qkv [24][965] = 23160 ; aliased: gstc [640][28]=17920 / head u
#define SC_OFF 38520                     // scores       [8][24][25]    4800
#define HH_OFF 43320                     // head LN vec  [320]
#define CC_OFF 43640                     // cheb coeffs  [64]
#define ST_OFF 43704                     // stats        [8]
#define SMEM_FLOATS 43712
#define SMEM_BYTES (SMEM_FLOATS * 4)

// Repacked weights (prep kernel fills these once per launch).
__device__ float g_Wqkvp[NL * 320 * 960];   // [l][k][ f4:160*4 | f2:160*2 ]  (o = 6*ct + j)
__device__ float g_Woutp[NL * 320 * 320];   // [l][k][o]   plain transpose (o = 2*ct + j)
__device__ float g_W1p[NL * 320 * 1280];    // [l][c][k][q]  q = 4*ct + j, o = c*640 + q
__device__ float g_W2p[NL * 1280 * 320];    // [l][c][kl][o] kl local ff idx, o = 2*ct + j
__device__ float g_Wh1t[320 * 320];

__global__ void prep_kernel(const float* __restrict__ Win, const float* __restrict__ Wout,
                            const float* __restrict__ W1, const float* __restrict__ W2,
                            const float* __restrict__ Wh1) {
    long start = (long)blockIdx.x * blockDim.x + threadIdx.x;
    long stride = (long)gridDim.x * blockDim.x;
    // QKV: split f4/f2 thread-major pack
    for (long i = start; i < (long)NL * 320 * 960; i += stride) {
        long l = i / 307200, r = i % 307200;
        long k = r / 960, q = r % 960;
        long o;
        if (q < 640) { long ct = q >> 2, e = q & 3; o = 6 * ct + e; }
        else         { long q2 = q - 640; long ct = q2 >> 1, e = q2 & 1; o = 6 * ct + 4 + e; }
        g_Wqkvp[i] = Win[l * 307200 + o * 320 + k];
    }
    for (long i = start; i < (long)NL * 320 * 320; i += stride) {
        long l = i / 102400, r = i % 102400;
        long k = r / 320, o = r % 320;
        g_Woutp[i] = Wout[l * 102400 + o * 320 + k];
    }
    for (long i = start; i < (long)NL * 2 * 320 * 640; i += stride) {
        long lc = i / 204800, r = i % 204800;
        long k = r / 640, q = r % 640;
        long l = lc / 2, c = lc % 2;
        g_W1p[i] = W1[l * 409600 + (c * 640 + q) * 320 + k];
    }
    for (long i = start; i < (long)NL * 2 * 640 * 320; i += stride) {
        long lc = i / 204800, r = i % 204800;
        long kl = r / 320, o = r % 320;
        long l = lc / 2, c = lc % 2;
        g_W2p[i] = W2[l * 409600 + o * 1280 + (c * 640 + kl)];
    }
    for (long i = start; i < (long)320 * 320; i += stride) {
        long k = i / 320, o = i % 320;
        g_Wh1t[i] = Wh1[o * 320 + k];
    }
}

__device__ __forceinline__ ull ffma2(ull a, ull b, ull c) {
    ull d;
    asm("fma.rn.f32x2 %0, %1, %2, %3;" : "=l"(d) : "l"(a), "l"(b), "l"(c));
    return d;
}
__device__ __forceinline__ ull bcast2(float x) {
    ull d;
    asm("mov.b64 %0, {%1, %1};" : "=l"(d) : "f"(x));
    return d;
}
__device__ __forceinline__ float2 unpack2(ull a) {
    float2 v;
    asm("mov.b64 {%0, %1}, %2;" : "=f"(v.x), "=f"(v.y) : "l"(a));
    return v;
}
__device__ __forceinline__ float gelu_exact(float x) {
    return 0.5f * x * (1.0f + erff(x * 0.70710678118654752f));
}
__device__ __forceinline__ float warp_sum(float v) {
#pragma unroll
    for (int o = 16; o; o >>= 1) v += __shfl_xor_sync(0xffffffffu, v, o);
    return v;
}

// Load this row-group's 4 activation row-pairs (8 rows), 16B-aligned broadcast.
__device__ __forceinline__ void lda4(ull* __restrict__ a, const ull* __restrict__ hp) {
    ulonglong2 q0 = *(const ulonglong2*)(hp);
    ulonglong2 q1 = *(const ulonglong2*)(hp + 2);
    a[0] = q0.x; a[1] = q0.y; a[2] = q1.x; a[3] = q1.y;
}

// One k-step of FMAs on preloaded activations: OUT weight-broadcast x 4 row-pairs.
template <int OUT>
__device__ __forceinline__ void fmaacc(const float* __restrict__ w, const ull* __restrict__ a,
                                       ull* __restrict__ acc) {
#pragma unroll
    for (int j = 0; j < OUT; j++) {
        ull wb = bcast2(w[j]);
        acc[j * 4 + 0] = ffma2(wb, a[0], acc[j * 4 + 0]);
        acc[j * 4 + 1] = ffma2(wb, a[1], acc[j * 4 + 1]);
        acc[j * 4 + 2] = ffma2(wb, a[2], acc[j * 4 + 2]);
        acc[j * 4 + 3] = ffma2(wb, a[3], acc[j * 4 + 3]);
    }
}

template <int G4, int G2>
__device__ __forceinline__ void ldw(float* __restrict__ w, const float* __restrict__ wk, int ct) {
    if (G4) {
        float4 v = __ldg((const float4*)(wk + ct * 4));
        w[0] = v.x; w[1] = v.y; w[2] = v.z; w[3] = v.w;
    }
    if (G2) {
        float2 v = __ldg((const float2*)(wk + G4 * 640 + ct * 2));
        w[4 * G4] = v.x; w[4 * G4 + 1] = v.y;
    }
}

// Register-blocked GEMM: 4-deep weight prefetch + double-buffered activations.
// Thread = (ct, rg): OUT consecutive output columns x 8 rows (4 f32x2 pairs).
// hin: ull pointer to this row-group's activation pairs; HSU ull stride per k.
template <int G4, int G2, int HSU>
__device__ __forceinline__ void gemmT(const float* __restrict__ Wp, int K, int ct,
                                      const ull* __restrict__ hin, ull* __restrict__ acc) {
    constexpr int OUT = 4 * G4 + 2 * G2;
    constexpr int WS = OUT * NCOL;
#pragma unroll
    for (int i = 0; i < OUT * 4; i++) acc[i] = 0ull;
    float w[4][OUT];
    ull a[2][4];
#pragma unroll
    for (int d = 0; d < 4; d++) ldw<G4, G2>(w[d], Wp + d * WS, ct);
    lda4(a[0], hin);
#pragma unroll 4
    for (int k = 0; k < K - 4; k++) {
        lda4(a[(k + 1) & 1], hin + (k + 1) * HSU);
        fmaacc<OUT>(w[k & 3], a[k & 1], acc);
        ldw<G4, G2>(w[k & 3], Wp + (k + 4) * WS, ct);
    }
#pragma unroll
    for (int k = K - 4; k < K - 1; k++) {
        lda4(a[(k + 1) & 1], hin + (k + 1) * HSU);
        fmaacc<OUT>(w[k & 3], a[k & 1], acc);
    }
    fmaacc<OUT>(w[3], a[1], acc);  // k = K-1: (K-1)&3 == 3, (K-1)&1 == 1 for K % 4 == 0
}

// LayerNorm of xs[24][320] -> transposed hst[k][HS]+r, one warp per row.
__device__ __forceinline__ void layernorm24(const float* __restrict__ xs, float* __restrict__ hst,
                                            const float* __restrict__ w, const float* __restrict__ b,
                                            int warp, int lane) {
    for (int r = warp; r < S; r += NWARP) {
        const float* row = xs + r * D;
        float s = 0.f;
        for (int k = lane; k < D; k += 32) s += row[k];
        s = warp_sum(s);
        float mean = s * (1.f / D);
        float s2 = 0.f;
        for (int k = lane; k < D; k += 32) {
            float v = row[k] - mean;
            s2 += v * v;
        }
        s2 = warp_sum(s2);
        float rstd = rsqrtf(s2 * (1.f / D) + 1e-5f);
        for (int k = lane; k < D; k += 32)
            hst[k * HS + r] = (row[k] - mean) * rstd * w[k] + b[k];
    }
}

__global__ __launch_bounds__(NT, 1) void fused_kernel(
    const float* __restrict__ k_norm, const float* __restrict__ ctx,
    const float* __restrict__ W_e, const float* __restrict__ b_e,
    const float* __restrict__ cls,
    const float* __restrict__ ln1_w, const float* __restrict__ ln1_b,
    const float* __restrict__ b_in, const float* __restrict__ b_out,
    const float* __restrict__ ln2_w, const float* __restrict__ ln2_b,
    const float* __restrict__ b1, const float* __restrict__ b2,
    const float* __restrict__ hln_w, const float* __restrict__ hln_b,
    const float* __restrict__ bh1, const float* __restrict__ Wh2,
    const float* __restrict__ bh2, float* __restrict__ out) {
    extern __shared__ float sm[];
    float* xs = sm + XS_OFF;
    float* hst = sm + HST_OFF;
    float* qv = sm + QV_OFF;
    float* gstc = sm + QV_OFF;   // ffn intermediate aliases qv: [640][28]
    float* sc = sm + SC_OFF;

    const int b = blockIdx.x;
    const int tid = threadIdx.x;
    const int warp = tid >> 5;
    const int lane = tid & 31;
    const int ct = tid % NCOL;       // warp-uniform row group (5 warps per rg)
    const int rg = tid / NCOL;       // 0..2
    const int rb = rg * 8;
    const ull* hstu = (const ull*)(hst) + rg * 4;
    const ull* gstu = (const ull*)(gstc) + rg * 4;

    // ---- build x: row 0 = cls, rows 1..23 = ctx*W_e + b_e ----
    for (int i = tid; i < S * D; i += NT) {
        int r = i / D, d = i % D;
        xs[i] = (r == 0) ? cls[d] : ctx[(long)b * CTXN + (r - 1)] * W_e[d] + b_e[d];
    }
    __syncthreads();

    for (int l = 0; l < NL; l++) {
        // ---- LN1 ----
        layernorm24(xs, hst, ln1_w + l * D, ln1_b + l * D, warp, lane);
        __syncthreads();

        // ---- QKV GEMM: 6 outputs x 8 rows per thread ----
        {
            ull acc[24];
            gemmT<1, 1, 12>(g_Wqkvp + l * 307200, 320, ct, hstu, acc);
            int ob = ct * 6;
#pragma unroll
            for (int j = 0; j < 6; j++) {
                int o = ob + j;
                float bias = b_in[l * 960 + o];
#pragma unroll
                for (int p = 0; p < 4; p++) {
                    float2 v = unpack2(acc[j * 4 + p]);
                    qv[(rb + 2 * p) * QVS + o] = v.x + bias;
                    qv[(rb + 2 * p + 1) * QVS + o] = v.y + bias;
                }
            }
        }
        __syncthreads();

        // ---- attention: one warp per head; output written transposed into hst ----
        if (warp < NH) {
            const int h = warp;
            const float scale = 0.15811388300841897f;  // 1/sqrt(40)
            for (int idx = lane; idx < S * S; idx += 32) {
                int qr = idx / S, kc = idx % S;
                const float* qp = qv + qr * QVS + h * DHD;
                const float* kp = qv + kc * QVS + D + h * DHD;
                float s = 0.f;
#pragma unroll
                for (int d = 0; d < DHD; d++) s += qp[d] * kp[d];
                sc[(h * S + qr) * 25 + kc] = s * scale;
            }
            __syncwarp();
            if (lane < S) {
                float* row = sc + (h * S + lane) * 25;
                float mx = -1e30f;
#pragma unroll
                for (int c = 0; c < S; c++) mx = fmaxf(mx, row[c]);
                float sum = 0.f;
#pragma unroll
                for (int c = 0; c < S; c++) {
                    float e = expf(row[c] - mx);
                    row[c] = e;
                    sum += e;
                }
                float inv = 1.f / sum;
#pragma unroll
                for (int c = 0; c < S; c++) row[c] *= inv;
            }
            __syncwarp();
            for (int idx = lane; idx < S * DHD; idx += 32) {
                int r = idx / DHD, d = idx % DHD;
                const float* ar = sc + (h * S + r) * 25;
                const float* vp = qv + 2 * D + h * DHD + d;
                float s = 0.f;
#pragma unroll
                for (int c = 0; c < S; c++) s += ar[c] * vp[c * QVS];
                hst[(h * DHD + d) * HS + r] = s;  // transposed attn output
            }
        }
        __syncthreads();

        // ---- output projection (residual add): 2 outputs x 8 rows ----
        {
            ull acc[8];
            gemmT<0, 1, 12>(g_Woutp + l * 102400, 320, ct, hstu, acc);
            int ob = ct * 2;
#pragma unroll
            for (int j = 0; j < 2; j++) {
                int o = ob + j;
                float bias = b_out[l * D + o];
#pragma unroll
                for (int p = 0; p < 4; p++) {
                    float2 v = unpack2(acc[j * 4 + p]);
                    xs[(rb + 2 * p) * D + o] += v.x + bias;
                    xs[(rb + 2 * p + 1) * D + o] += v.y + bias;
                }
            }
        }
        __syncthreads();

        // ---- LN2 ----
        layernorm24(xs, hst, ln2_w + l * D, ln2_b + l * D, warp, lane);
        __syncthreads();

        // ---- FFN: 2 chunks of 640 ff units ----
        for (int c = 0; c < 2; c++) {
            {
                ull acc[16];
                gemmT<1, 0, 12>(g_W1p + (l * 2 + c) * 204800, 320, ct, hstu, acc);
                int ob = ct * 4;
#pragma unroll
                for (int j = 0; j < 4; j++) {
                    int ol = ob + j;
                    float bias = b1[l * FFD + c * 640 + ol];
#pragma unroll
                    for (int p = 0; p < 4; p++) {
                        float2 v = unpack2(acc[j * 4 + p]);
                        float2 g;
                        g.x = gelu_exact(v.x + bias);
                        g.y = gelu_exact(v.y + bias);
                        *(float2*)(gstc + ol * GS + rb + 2 * p) = g;
                    }
                }
            }
            __syncthreads();
            {
                ull acc[8];
                gemmT<0, 1, 14>(g_W2p + (l * 2 + c) * 204800, 640, ct, gstu, acc);
                int ob = ct * 2;
#pragma unroll
                for (int j = 0; j < 2; j++) {
                    int o = ob + j;
                    float bias = (c == 0) ? b2[l * D + o] : 0.f;
#pragma unroll
                    for (int p = 0; p < 4; p++) {
                        float2 v = unpack2(acc[j * 4 + p]);
                        xs[(rb + 2 * p) * D + o] += v.x + bias;
                        xs[(rb + 2 * p + 1) * D + o] += v.y + bias;
                    }
                }
            }
            __syncthreads();
        }
    }

    // ---- head: LN(x[0]) ----
    if (warp == 0) {
        float s = 0.f;
        for (int k = lane; k < D; k += 32) s += xs[k];
        s = warp_sum(s);
        float mean = s * (1.f / D);
        float s2 = 0.f;
        for (int k = lane; k < D; k += 32) {
            float v = xs[k] - mean;
            s2 += v * v;
        }
        s2 = warp_sum(s2);
        if (lane == 0) {
            sm[ST_OFF] = mean;
            sm[ST_OFF + 1] = rsqrtf(s2 * (1.f / D) + 1e-5f);
        }
    }
    __syncthreads();
    if (tid < D) {
        float mean = sm[ST_OFF], rstd = sm[ST_OFF + 1];
        int k = tid;
        sm[HH_OFF + k] = (xs[k] - mean) * rstd * hln_w[k] + hln_b[k];
    }
    __syncthreads();

    // ---- u = gelu(hh @ Wh1^T + bh1): one output per thread (u aliases qv) ----
    if (tid < D) {
        int o = tid;
        float acc = bh1[o];
        const float* wp = g_Wh1t + o;
        const float* hh = sm + HH_OFF;
#pragma unroll 4
        for (int k = 0; k < D; k++) {
            acc = fmaf(hh[k], *wp, acc);
            wp += D;
        }
        qv[o] = gelu_exact(acc);
    }
    __syncthreads();

    // ---- c[j] = u @ Wh2^T + bh2 ----
    for (int j = warp; j < NCOEF; j += NWARP) {
        float s = 0.f;
        for (int k = lane; k < D; k += 32) s += qv[k] * Wh2[j * D + k];
        s = warp_sum(s);
        if (lane == 0) sm[CC_OFF + j] = s + bh2[j];
    }
    __syncthreads();

    // ---- Chebyshev sum + sigmoid over T=512 points ----
    const float* cc = sm + CC_OFF;
    for (int t = tid; t < TPTS; t += NT) {
        float x = k_norm[(long)b * TPTS + t];
        float tp = 1.f, tc = x;
        float z = cc[0] + cc[1] * x;
#pragma unroll
        for (int n = 2; n < NCOEF; n++) {
            float tn = 2.f * x * tc - tp;
            z = fmaf(cc[n], tn, z);
            tp = tc;
            tc = tn;
        }
        out[(long)b * TPTS + t] = 1.f / (1.f + expf(-z));
    }
}

extern "C" void kernel_launch(void* const* d_in, const int* in_sizes, int n_in,
                              void* d_out, int out_size) {
    (void)in_sizes; (void)n_in; (void)out_size;
    const float* k_norm = (const float*)d_in[0];
    const float* ctx = (const float*)d_in[1];
    const float* W_e = (const float*)d_in[2];
    const float* b_e = (const float*)d_in[3];
    const float* cls = (const float*)d_in[4];
    const float* ln1_w = (const float*)d_in[5];
    const float* ln1_b = (const float*)d_in[6];
    const float* W_in = (const float*)d_in[7];
    const float* b_in = (const float*)d_in[8];
    const float* W_out = (const float*)d_in[9];
    const float* b_out = (const float*)d_in[10];
    const float* ln2_w = (const float*)d_in[11];
    const float* ln2_b = (const float*)d_in[12];
    const float* W1 = (const float*)d_in[13];
    const float* b1 = (const float*)d_in[14];
    const float* W2 = (const float*)d_in[15];
    const float* b2 = (const float*)d_in[16];
    const float* hln_w = (const float*)d_in[17];
    const float* hln_b = (const float*)d_in[18];
    const float* Wh1 = (const float*)d_in[19];
    const float* bh1 = (const float*)d_in[20];
    const float* Wh2 = (const float*)d_in[21];
    const float* bh2 = (const float*)d_in[22];
    float* out = (float*)d_out;

    cudaFuncSetAttribute(fused_kernel, cudaFuncAttributeMaxDynamicSharedMemorySize, SMEM_BYTES);

    prep_kernel<<<512, 256>>>(W_in, W_out, W1, W2, Wh1);
    fused_kernel<<<NB, NT, SMEM_BYTES>>>(k_norm, ctx, W_e, b_e, cls, ln1_w, ln1_b,
                                         b_in, b_out, ln2_w, ln2_b, b1, b2,
                                         hln_w, hln_b, bh1, Wh2, bh2, out);
}